// round 4
// baseline (speedup 1.0000x reference)
#include <cuda_runtime.h>
#include <math.h>

#define H_ 256
#define W_ 256
#define B_ 8
#define HW (H_ * W_)
#define KF 11
#define THRESH 0.2f

// Scratch ping-pong buffers (max 128 channels)
__device__ float g_bufA[(size_t)B_ * 128 * HW];
__device__ float g_bufB[(size_t)B_ * 128 * HW];

// ---------------------------------------------------------------------------
// concat rgb(3) + depth(1) -> 4-channel NCHW
// ---------------------------------------------------------------------------
__global__ void concat_kernel(const float* __restrict__ rgb,
                              const float* __restrict__ depth,
                              float* __restrict__ out) {
    int i = blockIdx.x * blockDim.x + threadIdx.x;
    if (i >= B_ * 4 * HW) return;
    int px = i % HW;
    int c = (i / HW) % 4;
    int b = i / (4 * HW);
    out[i] = (c < 3) ? rgb[((size_t)b * 3 + c) * HW + px]
                     : depth[(size_t)b * HW + px];
}

// ---------------------------------------------------------------------------
// Generic 3x3 SAME conv, NCHW. Block = 16x16 threads -> 32x32 output tile.
// Each thread: 2x2 pixels x 8 output channels (32 accumulators).
// Input channels processed in chunks of 4 via shared memory.
// ---------------------------------------------------------------------------
template <int CIN, int COUT, bool RELU>
__global__ __launch_bounds__(256)
void conv3x3_kernel(const float* __restrict__ in, const float* __restrict__ w,
                    const float* __restrict__ bias, float* __restrict__ out) {
    constexpr int OCB = 8;
    __shared__ float s_in[4][34 * 34];
    __shared__ float s_w[4][OCB][9];

    const int tx = threadIdx.x, ty = threadIdx.y;
    const int tid = ty * 16 + tx;
    const int bz = blockIdx.z;
    const int b = bz / (COUT / OCB);
    const int oc0 = (bz % (COUT / OCB)) * OCB;
    const int gx0 = blockIdx.x * 32 - 1;
    const int gy0 = blockIdx.y * 32 - 1;

    float acc[OCB][4];
#pragma unroll
    for (int oc = 0; oc < OCB; oc++) {
        float bv = bias[oc0 + oc];
        acc[oc][0] = bv; acc[oc][1] = bv; acc[oc][2] = bv; acc[oc][3] = bv;
    }

    for (int ci0 = 0; ci0 < CIN; ci0 += 4) {
        __syncthreads();
        // load 4 input-channel tiles (34x34 with halo)
        for (int idx = tid; idx < 4 * 34 * 34; idx += 256) {
            int ch = idx / (34 * 34);
            int rem = idx % (34 * 34);
            int r = rem / 34, c = rem % 34;
            int gy = gy0 + r, gx = gx0 + c;
            float v = 0.f;
            if (gy >= 0 && gy < H_ && gx >= 0 && gx < W_)
                v = in[(((size_t)b * CIN + ci0 + ch) * H_ + gy) * W_ + gx];
            s_in[ch][rem] = v;
        }
        // load weights for 4 cin x 8 oc
        for (int idx = tid; idx < 4 * OCB * 9; idx += 256) {
            int oc = idx / 36;
            int rem = idx % 36;
            int ch = rem / 9, t = rem % 9;
            s_w[ch][oc][t] = w[(((size_t)(oc0 + oc)) * CIN + ci0 + ch) * 9 + t];
        }
        __syncthreads();

#pragma unroll
        for (int ch = 0; ch < 4; ch++) {
            float in_r[4][4];
#pragma unroll
            for (int r = 0; r < 4; r++)
#pragma unroll
                for (int c = 0; c < 4; c++)
                    in_r[r][c] = s_in[ch][(2 * ty + r) * 34 + 2 * tx + c];
#pragma unroll
            for (int ky = 0; ky < 3; ky++)
#pragma unroll
                for (int kx = 0; kx < 3; kx++) {
#pragma unroll
                    for (int oc = 0; oc < OCB; oc++) {
                        float wv = s_w[ch][oc][ky * 3 + kx];
                        acc[oc][0] = fmaf(wv, in_r[ky][kx],         acc[oc][0]);
                        acc[oc][1] = fmaf(wv, in_r[ky][kx + 1],     acc[oc][1]);
                        acc[oc][2] = fmaf(wv, in_r[ky + 1][kx],     acc[oc][2]);
                        acc[oc][3] = fmaf(wv, in_r[ky + 1][kx + 1], acc[oc][3]);
                    }
                }
        }
    }

    const int oy = blockIdx.y * 32 + 2 * ty;
    const int ox = blockIdx.x * 32 + 2 * tx;
#pragma unroll
    for (int oc = 0; oc < OCB; oc++) {
#pragma unroll
        for (int p = 0; p < 4; p++) {
            float v = acc[oc][p];
            if (RELU) v = fmaxf(v, 0.f);
            out[(((size_t)b * COUT + oc0 + oc) * H_ + oy + (p >> 1)) * W_ + ox + (p & 1)] = v;
        }
    }
}

// ---------------------------------------------------------------------------
// Kernel-prediction: conv 64->22 (wh stacked with wv) + per-group softmax(11)
// Same tiling as conv3x3_kernel, 22 channels per thread-pixel.
// ---------------------------------------------------------------------------
__global__ __launch_bounds__(256)
void kpred_kernel(const float* __restrict__ in,
                  const float* __restrict__ wh, const float* __restrict__ bh,
                  const float* __restrict__ wv, const float* __restrict__ bv,
                  float* __restrict__ kh_out, float* __restrict__ kv_out) {
    constexpr int CIN = 64;
    constexpr int OCB = 22;
    __shared__ float s_in[4][34 * 34];
    __shared__ float s_w[4][OCB][9];

    const int tx = threadIdx.x, ty = threadIdx.y;
    const int tid = ty * 16 + tx;
    const int b = blockIdx.z;
    const int gx0 = blockIdx.x * 32 - 1;
    const int gy0 = blockIdx.y * 32 - 1;

    float acc[OCB][4];
#pragma unroll
    for (int o = 0; o < OCB; o++) {
        float bval = (o < KF) ? bh[o] : bv[o - KF];
        acc[o][0] = bval; acc[o][1] = bval; acc[o][2] = bval; acc[o][3] = bval;
    }

    for (int ci0 = 0; ci0 < CIN; ci0 += 4) {
        __syncthreads();
        for (int idx = tid; idx < 4 * 34 * 34; idx += 256) {
            int ch = idx / (34 * 34);
            int rem = idx % (34 * 34);
            int r = rem / 34, c = rem % 34;
            int gy = gy0 + r, gx = gx0 + c;
            float v = 0.f;
            if (gy >= 0 && gy < H_ && gx >= 0 && gx < W_)
                v = in[(((size_t)b * CIN + ci0 + ch) * H_ + gy) * W_ + gx];
            s_in[ch][rem] = v;
        }
        for (int idx = tid; idx < 4 * OCB * 9; idx += 256) {
            int o = idx / 36;
            int rem = idx % 36;
            int ch = rem / 9, t = rem % 9;
            float wv_;
            if (o < KF) wv_ = wh[(((size_t)o) * CIN + ci0 + ch) * 9 + t];
            else        wv_ = wv[(((size_t)(o - KF)) * CIN + ci0 + ch) * 9 + t];
            s_w[ch][o][t] = wv_;
        }
        __syncthreads();

#pragma unroll
        for (int ch = 0; ch < 4; ch++) {
            float in_r[4][4];
#pragma unroll
            for (int r = 0; r < 4; r++)
#pragma unroll
                for (int c = 0; c < 4; c++)
                    in_r[r][c] = s_in[ch][(2 * ty + r) * 34 + 2 * tx + c];
#pragma unroll
            for (int ky = 0; ky < 3; ky++)
#pragma unroll
                for (int kx = 0; kx < 3; kx++) {
#pragma unroll
                    for (int o = 0; o < OCB; o++) {
                        float wv_ = s_w[ch][o][ky * 3 + kx];
                        acc[o][0] = fmaf(wv_, in_r[ky][kx],         acc[o][0]);
                        acc[o][1] = fmaf(wv_, in_r[ky][kx + 1],     acc[o][1]);
                        acc[o][2] = fmaf(wv_, in_r[ky + 1][kx],     acc[o][2]);
                        acc[o][3] = fmaf(wv_, in_r[ky + 1][kx + 1], acc[o][3]);
                    }
                }
        }
    }

    const int oy0 = blockIdx.y * 32 + 2 * ty;
    const int ox0 = blockIdx.x * 32 + 2 * tx;
#pragma unroll
    for (int p = 0; p < 4; p++) {
        int oy = oy0 + (p >> 1);
        int ox = ox0 + (p & 1);
        // softmax over kh group (0..10)
        {
            float m = acc[0][p];
#pragma unroll
            for (int i = 1; i < KF; i++) m = fmaxf(m, acc[i][p]);
            float e[KF];
            float s = 0.f;
#pragma unroll
            for (int i = 0; i < KF; i++) { e[i] = expf(acc[i][p] - m); s += e[i]; }
            float inv = 1.f / s;
#pragma unroll
            for (int i = 0; i < KF; i++)
                kh_out[(((size_t)b * KF + i) * H_ + oy) * W_ + ox] = e[i] * inv;
        }
        // softmax over kv group (11..21)
        {
            float m = acc[KF][p];
#pragma unroll
            for (int i = 1; i < KF; i++) m = fmaxf(m, acc[KF + i][p]);
            float e[KF];
            float s = 0.f;
#pragma unroll
            for (int i = 0; i < KF; i++) { e[i] = expf(acc[KF + i][p] - m); s += e[i]; }
            float inv = 1.f / s;
#pragma unroll
            for (int i = 0; i < KF; i++)
                kv_out[(((size_t)b * KF + i) * H_ + oy) * W_ + ox] = e[i] * inv;
        }
    }
}

// ---------------------------------------------------------------------------
// Horizontal pass of the dynamic separable filter.
// One block per (row, batch); 256 threads = one per column.
// ---------------------------------------------------------------------------
__global__ __launch_bounds__(256)
void hblur_kernel(const float* __restrict__ rgb, const float* __restrict__ kh,
                  float* __restrict__ hout) {
    __shared__ float srow[3][W_ + 2 * 5];
    const int x = threadIdx.x;
    const int y = blockIdx.x;
    const int b = blockIdx.y;

#pragma unroll
    for (int c = 0; c < 3; c++)
        srow[c][x + 5] = rgb[(((size_t)b * 3 + c) * H_ + y) * W_ + x];
    if (x < 5) {
#pragma unroll
        for (int c = 0; c < 3; c++) {
            srow[c][x] = 0.f;
            srow[c][W_ + 5 + x] = 0.f;
        }
    }
    __syncthreads();

    float k[KF];
#pragma unroll
    for (int i = 0; i < KF; i++)
        k[i] = kh[(((size_t)b * KF + i) * H_ + y) * W_ + x];

#pragma unroll
    for (int c = 0; c < 3; c++) {
        float s = 0.f;
#pragma unroll
        for (int i = 0; i < KF; i++) s = fmaf(k[i], srow[c][x + i], s);
        hout[(((size_t)b * 3 + c) * H_ + y) * W_ + x] = s;
    }
}

// ---------------------------------------------------------------------------
// Vertical pass + depth-mask composite. Writes final, blurred, mask.
// ---------------------------------------------------------------------------
__global__ __launch_bounds__(256)
void vblur_kernel(const float* __restrict__ hbuf, const float* __restrict__ kv,
                  const float* __restrict__ rgb, const float* __restrict__ depth,
                  float* __restrict__ fin, float* __restrict__ blur,
                  float* __restrict__ mask) {
    const int x = threadIdx.x;
    const int y = blockIdx.x;
    const int b = blockIdx.y;

    float k[KF];
#pragma unroll
    for (int i = 0; i < KF; i++)
        k[i] = kv[(((size_t)b * KF + i) * H_ + y) * W_ + x];

    float d = depth[((size_t)b * H_ + y) * W_ + x];
    float m = (d > THRESH) ? 1.f : 0.f;

#pragma unroll
    for (int c = 0; c < 3; c++) {
        float s = 0.f;
#pragma unroll
        for (int i = 0; i < KF; i++) {
            int yy = y - 5 + i;
            if (yy >= 0 && yy < H_)
                s = fmaf(k[i], hbuf[(((size_t)b * 3 + c) * H_ + yy) * W_ + x], s);
        }
        size_t oidx = (((size_t)b * 3 + c) * H_ + y) * W_ + x;
        float r = rgb[oidx];
        blur[oidx] = s;
        fin[oidx] = m * r + (1.f - m) * s;
    }
    mask[((size_t)b * H_ + y) * W_ + x] = m;
}

// ---------------------------------------------------------------------------
extern "C" void kernel_launch(void* const* d_in, const int* in_sizes, int n_in,
                              void* d_out, int out_size) {
    const float* rgb   = (const float*)d_in[0];
    const float* depth = (const float*)d_in[1];
    const float* w1 = (const float*)d_in[2];
    const float* b1 = (const float*)d_in[3];
    const float* w2 = (const float*)d_in[4];
    const float* b2 = (const float*)d_in[5];
    const float* w3 = (const float*)d_in[6];
    const float* b3 = (const float*)d_in[7];
    const float* w4 = (const float*)d_in[8];
    const float* b4 = (const float*)d_in[9];
    const float* w5 = (const float*)d_in[10];
    const float* b5 = (const float*)d_in[11];
    const float* wh = (const float*)d_in[12];
    const float* bh = (const float*)d_in[13];
    const float* wv = (const float*)d_in[14];
    const float* bv = (const float*)d_in[15];

    float* out = (float*)d_out;
    float* fin_o  = out;
    float* blur_o = out + (size_t)B_ * 3 * HW;
    float* kh_o   = out + (size_t)2 * B_ * 3 * HW;
    float* kv_o   = kh_o + (size_t)B_ * KF * HW;
    float* mask_o = kv_o + (size_t)B_ * KF * HW;

    float* bufA = nullptr;
    float* bufB = nullptr;
    cudaGetSymbolAddress((void**)&bufA, g_bufA);
    cudaGetSymbolAddress((void**)&bufB, g_bufB);

    // concat rgb+depth into bufB (4 channels)
    {
        int n = B_ * 4 * HW;
        concat_kernel<<<(n + 255) / 256, 256>>>(rgb, depth, bufB);
    }

    dim3 blk(16, 16);
    // conv1: 4 -> 64, bufB -> bufA
    conv3x3_kernel<4, 64, true><<<dim3(W_ / 32, H_ / 32, B_ * (64 / 8)), blk>>>(bufB, w1, b1, bufA);
    // conv2: 64 -> 64, bufA -> bufB
    conv3x3_kernel<64, 64, true><<<dim3(W_ / 32, H_ / 32, B_ * (64 / 8)), blk>>>(bufA, w2, b2, bufB);
    // conv3: 64 -> 128, bufB -> bufA
    conv3x3_kernel<64, 128, true><<<dim3(W_ / 32, H_ / 32, B_ * (128 / 8)), blk>>>(bufB, w3, b3, bufA);
    // conv4: 128 -> 128, bufA -> bufB
    conv3x3_kernel<128, 128, true><<<dim3(W_ / 32, H_ / 32, B_ * (128 / 8)), blk>>>(bufA, w4, b4, bufB);
    // conv5: 128 -> 64, bufB -> bufA
    conv3x3_kernel<128, 64, true><<<dim3(W_ / 32, H_ / 32, B_ * (64 / 8)), blk>>>(bufB, w5, b5, bufA);
    // kernel prediction + softmax: bufA -> kh_o, kv_o
    kpred_kernel<<<dim3(W_ / 32, H_ / 32, B_), blk>>>(bufA, wh, bh, wv, bv, kh_o, kv_o);
    // horizontal blur: rgb, kh -> bufB (3ch)
    hblur_kernel<<<dim3(H_, B_), 256>>>(rgb, kh_o, bufB);
    // vertical blur + composite
    vblur_kernel<<<dim3(H_, B_), 256>>>(bufB, kv_o, rgb, depth, fin_o, blur_o, mask_o);
}

// round 7
// speedup vs baseline: 8.0423x; 8.0423x over previous
#include <cuda_runtime.h>
#include <cuda_bf16.h>
#include <cstdint>
#include <math.h>

#define H_ 256
#define W_ 256
#define B_ 8
#define HW (H_ * W_)
#define KF 11
#define THRESH 0.2f

// ---------------------------------------------------------------------------
// Device scratch (no allocation allowed)
// ---------------------------------------------------------------------------
__device__ __nv_bfloat16 g_bufA[(size_t)B_ * 128 * HW];   // NHWC activations ping
__device__ __nv_bfloat16 g_bufB[(size_t)B_ * 128 * HW];   // NHWC pong / fp32 scratch
// Packed weights: [ky][kp][NP][2] bf16, k = kp*2+h in [0, 3C)
__device__ __nv_bfloat16 g_wt2[3 * 96 * 64 * 2];
__device__ __nv_bfloat16 g_wt3[3 * 96 * 128 * 2];
__device__ __nv_bfloat16 g_wt4[3 * 192 * 128 * 2];
__device__ __nv_bfloat16 g_wt5[3 * 192 * 64 * 2];
__device__ __nv_bfloat16 g_wtp[3 * 96 * 32 * 2];

__device__ __forceinline__ uint32_t smem_u32(const void* p) {
    uint32_t a;
    asm("{ .reg .u64 t; cvta.to.shared.u64 t, %1; cvt.u32.u64 %0, t; }" : "=r"(a) : "l"(p));
    return a;
}

__device__ __forceinline__ void ldmatrix_x4(uint32_t* a, uint32_t addr) {
    asm volatile("ldmatrix.sync.aligned.m8n8.x4.shared.b16 {%0,%1,%2,%3}, [%4];"
                 : "=r"(a[0]), "=r"(a[1]), "=r"(a[2]), "=r"(a[3]) : "r"(addr));
}

__device__ __forceinline__ void mma_bf16(float* d, const uint32_t* a, const uint32_t* b) {
    asm volatile(
        "mma.sync.aligned.m16n8k16.row.col.f32.bf16.bf16.f32 "
        "{%0,%1,%2,%3}, {%4,%5,%6,%7}, {%8,%9}, {%0,%1,%2,%3};"
        : "+f"(d[0]), "+f"(d[1]), "+f"(d[2]), "+f"(d[3])
        : "r"(a[0]), "r"(a[1]), "r"(a[2]), "r"(a[3]), "r"(b[0]), "r"(b[1]));
}

// ---------------------------------------------------------------------------
// Weight packing: w[COUT][CIN][3][3] fp32 -> wtP[ky][kp][NP][2] bf16
// k = kp*2+h in [0,3C): kx = k/C, ci = k%C
// ---------------------------------------------------------------------------
template <int CIN, int COUT, int NP>
__global__ void packw_kernel(const float* __restrict__ w, __nv_bfloat16* __restrict__ wt) {
    int i = blockIdx.x * 256 + threadIdx.x;
    constexpr int KP = 3 * CIN / 2;
    int total = 3 * KP * NP * 2;
    if (i >= total) return;
    int h = i & 1;
    int n = (i >> 1) % NP;
    int kp = (i >> 1) / NP % KP;
    int ky = i / (2 * NP * KP);
    int k = kp * 2 + h;
    int kx = k / CIN, ci = k % CIN;
    float v = (n < COUT) ? w[((size_t)n * CIN + ci) * 9 + ky * 3 + kx] : 0.f;
    wt[i] = __float2bfloat16(v);
}

// kpred weights: n 0..10 = wh, 11..21 = wv, rest 0. CIN=64, NP=32
__global__ void packw_p_kernel(const float* __restrict__ wh, const float* __restrict__ wv,
                               __nv_bfloat16* __restrict__ wt) {
    int i = blockIdx.x * 256 + threadIdx.x;
    constexpr int KP = 96;
    int total = 3 * KP * 32 * 2;
    if (i >= total) return;
    int h = i & 1;
    int n = (i >> 1) % 32;
    int kp = (i >> 1) / 32 % KP;
    int ky = i / (2 * 32 * KP);
    int k = kp * 2 + h;
    int kx = k / 64, ci = k % 64;
    float v = 0.f;
    if (n < KF)          v = wh[((size_t)n * 64 + ci) * 9 + ky * 3 + kx];
    else if (n < 2 * KF) v = wv[((size_t)(n - KF) * 64 + ci) * 9 + ky * 3 + kx];
    wt[i] = __float2bfloat16(v);
}

// ---------------------------------------------------------------------------
// conv1: 4 -> 64, fp32 direct, NCHW fp32 in -> bf16 NHWC out
// ---------------------------------------------------------------------------
__global__ __launch_bounds__(256)
void conv1_kernel(const float* __restrict__ rgb, const float* __restrict__ depth,
                  const float* __restrict__ w1, const float* __restrict__ b1,
                  __nv_bfloat16* __restrict__ out) {
    __shared__ float sw[64 * 36];
    __shared__ float sb[64];
    int tid = threadIdx.x;
    for (int i = tid; i < 64 * 36; i += 256) sw[i] = w1[i];
    if (tid < 64) sb[tid] = b1[tid];
    __syncthreads();

    int gp = blockIdx.x * 256 + tid;
    int x = gp % W_;
    int y = (gp / W_) % H_;
    int b = gp / HW;

    float acc[64];
#pragma unroll
    for (int o = 0; o < 64; o++) acc[o] = sb[o];

    for (int ci = 0; ci < 4; ci++) {
        const float* plane = (ci < 3) ? rgb + ((size_t)b * 3 + ci) * HW
                                      : depth + (size_t)b * HW;
#pragma unroll
        for (int dy = -1; dy <= 1; dy++) {
#pragma unroll
            for (int dx = -1; dx <= 1; dx++) {
                int yy = y + dy, xx = x + dx;
                float v = (yy >= 0 && yy < H_ && xx >= 0 && xx < W_) ? plane[yy * W_ + xx] : 0.f;
                int widx = ci * 9 + (dy + 1) * 3 + (dx + 1);
#pragma unroll
                for (int o = 0; o < 64; o++) acc[o] = fmaf(sw[o * 36 + widx], v, acc[o]);
            }
        }
    }
    __nv_bfloat16* op = out + (size_t)gp * 64;
#pragma unroll
    for (int o = 0; o < 64; o += 2) {
        __nv_bfloat162 h = __floats2bfloat162_rn(fmaxf(acc[o], 0.f), fmaxf(acc[o + 1], 0.f));
        *(__nv_bfloat162*)(op + o) = h;
    }
}

// ---------------------------------------------------------------------------
// Implicit-GEMM 3x3 conv via mma.sync (bf16 HMMA, fp32 acc).
// in: NHWC bf16 [B,H,W,C]; out: NHWC bf16 [B,H,W,NP] (or fp32 if F32OUT).
// CTA: 128 pixels x NTILE outputs. 8 warps: 4 (M) x 2 (N); warp 32 x NTILE/2.
// ---------------------------------------------------------------------------
template <int C, int NTILE, int NP, bool RELU, bool F32OUT>
__global__ __launch_bounds__(256)
void convmma_kernel(const __nv_bfloat16* __restrict__ in,
                    const __nv_bfloat16* __restrict__ wtP,
                    const float* __restrict__ bias,
                    void* __restrict__ outv) {
    constexpr int SA = C + 8;                // A row stride (halves)
    constexpr int BST = NTILE * 2 + 16;      // B kp-row stride (halves)
    constexpr int KP3 = 3 * C / 2;           // kp rows per ky
    constexpr int NSTEP = 3 * C / 16;        // k16 steps per ky
    constexpr int KXW = C / 16;              // steps per kx
    constexpr int WN = NTILE / 2;            // warp n width
    constexpr int NBK = WN / 8;              // n-blocks per warp
    constexpr int ASZ = 130 * SA * 2;        // bytes
    constexpr int CH8 = C / 8;               // uint4 per A row
    constexpr int NU4 = NTILE / 4;           // uint4 per B kp row (NTILE pairs = NTILE*4 bytes)

    extern __shared__ char smem_raw[];
    char* sA = smem_raw;
    char* sB = smem_raw + ASZ;
    const uint32_t sA_u = smem_u32(sA);

    __shared__ float s_bias[NTILE];

    const int tid = threadIdx.x;
    const int wid = tid >> 5;
    const int lane = tid & 31;
    const int wm = wid & 3;          // M warp (0..3)
    const int wn = wid >> 2;         // N warp (0..1)
    const int x0 = blockIdx.x * 128;
    const int y = blockIdx.y;
    constexpr int NTILES = NP / NTILE;
    const int b = blockIdx.z / NTILES;
    const int n0 = (blockIdx.z % NTILES) * NTILE;

    if (!F32OUT && tid < NTILE) s_bias[tid] = bias[n0 + tid];

    float acc[2][NBK][4];
#pragma unroll
    for (int mb = 0; mb < 2; mb++)
#pragma unroll
        for (int nb = 0; nb < NBK; nb++)
#pragma unroll
            for (int q = 0; q < 4; q++) acc[mb][nb][q] = 0.f;

    const int lane_row = lane & 15;
    const int colsel = (lane >> 4) * 8;

    for (int ky = 0; ky < 3; ky++) {
        const int yy = y + ky - 1;
        const bool rowok = (yy >= 0 && yy < H_);
        const __nv_bfloat16* inrow = in + (((size_t)b * H_ + (rowok ? yy : 0)) * W_) * C;
        if (ky) __syncthreads();
        // ---- A tile: 130 pixels x C halves ----
        for (int it = tid; it < 130 * CH8; it += 256) {
            int p = it / CH8;
            int c8 = it - p * CH8;
            int xx = x0 + p - 1;
            uint4 v = make_uint4(0u, 0u, 0u, 0u);
            if (rowok && xx >= 0 && xx < W_)
                v = *(const uint4*)(inrow + (size_t)xx * C + c8 * 8);
            *(uint4*)(sA + (p * SA + c8 * 8) * 2) = v;
        }
        // ---- B tile: KP3 kp-rows x NTILE pairs (NU4 uint4 per row) ----
        {
            const __nv_bfloat16* wsrc = wtP + ((size_t)ky * KP3 * NP + n0) * 2;
            for (int it = tid; it < KP3 * NU4; it += 256) {
                int kp = it / NU4;
                int q = it - kp * NU4;
                uint4 v = *(const uint4*)(wsrc + (size_t)kp * NP * 2 + q * 8);
                *(uint4*)(sB + (kp * BST + q * 8) * 2) = v;
            }
        }
        __syncthreads();

        // ---- compute ----
#pragma unroll
        for (int s = 0; s < NSTEP; s++) {
            const int kx = s / KXW;
            const int c0 = (s - kx * KXW) * 16;
            uint32_t afr[2][4];
#pragma unroll
            for (int mb = 0; mb < 2; mb++) {
                uint32_t addr = sA_u +
                    ((wm * 32 + mb * 16 + lane_row + kx) * SA + c0 + colsel) * 2;
                ldmatrix_x4(afr[mb], addr);
            }
            uint32_t bfr[NBK][2];
#pragma unroll
            for (int nb = 0; nb < NBK; nb++) {
                int n = wn * WN + nb * 8 + (lane >> 2);
#pragma unroll
                for (int r = 0; r < 2; r++) {
                    int kp = s * 8 + (lane & 3) + r * 4;
                    bfr[nb][r] = *(const uint32_t*)(sB + (kp * BST + n * 2) * 2);
                }
            }
#pragma unroll
            for (int mb = 0; mb < 2; mb++)
#pragma unroll
                for (int nb = 0; nb < NBK; nb++)
                    mma_bf16(acc[mb][nb], afr[mb], bfr[nb]);
        }
    }
    __syncthreads();

    // ---- epilogue ----
    const int g = lane >> 2;
    const int cpair = (lane & 3) * 2;
#pragma unroll
    for (int mb = 0; mb < 2; mb++) {
#pragma unroll
        for (int half = 0; half < 2; half++) {
            int m = wm * 32 + mb * 16 + g + half * 8;
            size_t pix = ((size_t)b * H_ + y) * W_ + x0 + m;
#pragma unroll
            for (int nb = 0; nb < NBK; nb++) {
                int col = wn * WN + nb * 8 + cpair;
                float f0 = acc[mb][nb][half * 2 + 0];
                float f1 = acc[mb][nb][half * 2 + 1];
                if (F32OUT) {
                    float* op = (float*)outv + pix * NP + n0 + col;
                    *(float2*)op = make_float2(f0, f1);
                } else {
                    f0 += s_bias[col];
                    f1 += s_bias[col + 1];
                    if (RELU) { f0 = fmaxf(f0, 0.f); f1 = fmaxf(f1, 0.f); }
                    __nv_bfloat162 h = __floats2bfloat162_rn(f0, f1);
                    __nv_bfloat16* op = (__nv_bfloat16*)outv + pix * NP + n0 + col;
                    *(uint32_t*)op = *(uint32_t*)&h;
                }
            }
        }
    }
}

// ---------------------------------------------------------------------------
// softmax over logits [B,H,W,32] fp32 -> kh, kv NCHW fp32
// ---------------------------------------------------------------------------
__global__ __launch_bounds__(256)
void softmax_kernel(const float* __restrict__ logits,
                    const float* __restrict__ bh, const float* __restrict__ bv,
                    float* __restrict__ kh_out, float* __restrict__ kv_out) {
    __shared__ float sbh[KF], sbv[KF];
    int tid = threadIdx.x;
    if (tid < KF) { sbh[tid] = bh[tid]; sbv[tid] = bv[tid]; }
    __syncthreads();

    int gp = blockIdx.x * 256 + tid;
    int px = gp % HW;
    int b = gp / HW;
    int y = px / W_, x = px % W_;
    const float* lp = logits + (size_t)gp * 32;

    float l[KF];
#pragma unroll
    for (int i = 0; i < KF; i++) l[i] = lp[i] + sbh[i];
    float mx = l[0];
#pragma unroll
    for (int i = 1; i < KF; i++) mx = fmaxf(mx, l[i]);
    float e[KF], s = 0.f;
#pragma unroll
    for (int i = 0; i < KF; i++) { e[i] = expf(l[i] - mx); s += e[i]; }
    float inv = 1.f / s;
#pragma unroll
    for (int i = 0; i < KF; i++)
        kh_out[(((size_t)b * KF + i) * H_ + y) * W_ + x] = e[i] * inv;

#pragma unroll
    for (int i = 0; i < KF; i++) l[i] = lp[KF + i] + sbv[i];
    mx = l[0];
#pragma unroll
    for (int i = 1; i < KF; i++) mx = fmaxf(mx, l[i]);
    s = 0.f;
#pragma unroll
    for (int i = 0; i < KF; i++) { e[i] = expf(l[i] - mx); s += e[i]; }
    inv = 1.f / s;
#pragma unroll
    for (int i = 0; i < KF; i++)
        kv_out[(((size_t)b * KF + i) * H_ + y) * W_ + x] = e[i] * inv;
}

// ---------------------------------------------------------------------------
// Separable blur + composite (fp32)
// ---------------------------------------------------------------------------
__global__ __launch_bounds__(256)
void hblur_kernel(const float* __restrict__ rgb, const float* __restrict__ kh,
                  float* __restrict__ hout) {
    __shared__ float srow[3][W_ + 10];
    const int x = threadIdx.x;
    const int y = blockIdx.x;
    const int b = blockIdx.y;

#pragma unroll
    for (int c = 0; c < 3; c++)
        srow[c][x + 5] = rgb[(((size_t)b * 3 + c) * H_ + y) * W_ + x];
    if (x < 5) {
#pragma unroll
        for (int c = 0; c < 3; c++) { srow[c][x] = 0.f; srow[c][W_ + 5 + x] = 0.f; }
    }
    __syncthreads();

    float k[KF];
#pragma unroll
    for (int i = 0; i < KF; i++)
        k[i] = kh[(((size_t)b * KF + i) * H_ + y) * W_ + x];

#pragma unroll
    for (int c = 0; c < 3; c++) {
        float s = 0.f;
#pragma unroll
        for (int i = 0; i < KF; i++) s = fmaf(k[i], srow[c][x + i], s);
        hout[(((size_t)b * 3 + c) * H_ + y) * W_ + x] = s;
    }
}

__global__ __launch_bounds__(256)
void vblur_kernel(const float* __restrict__ hbuf, const float* __restrict__ kv,
                  const float* __restrict__ rgb, const float* __restrict__ depth,
                  float* __restrict__ fin, float* __restrict__ blur,
                  float* __restrict__ mask) {
    const int x = threadIdx.x;
    const int y = blockIdx.x;
    const int b = blockIdx.y;

    float k[KF];
#pragma unroll
    for (int i = 0; i < KF; i++)
        k[i] = kv[(((size_t)b * KF + i) * H_ + y) * W_ + x];

    float d = depth[((size_t)b * H_ + y) * W_ + x];
    float m = (d > THRESH) ? 1.f : 0.f;

#pragma unroll
    for (int c = 0; c < 3; c++) {
        float s = 0.f;
#pragma unroll
        for (int i = 0; i < KF; i++) {
            int yy = y - 5 + i;
            if (yy >= 0 && yy < H_)
                s = fmaf(k[i], hbuf[(((size_t)b * 3 + c) * H_ + yy) * W_ + x], s);
        }
        size_t oidx = (((size_t)b * 3 + c) * H_ + y) * W_ + x;
        float r = rgb[oidx];
        blur[oidx] = s;
        fin[oidx] = m * r + (1.f - m) * s;
    }
    mask[((size_t)b * H_ + y) * W_ + x] = m;
}

// ---------------------------------------------------------------------------
static inline int convmma_smem(int C, int NTILE) {
    int SA = C + 8;
    int BST = NTILE * 2 + 16;
    return 130 * SA * 2 + (3 * C / 2) * BST * 2;
}

extern "C" void kernel_launch(void* const* d_in, const int* in_sizes, int n_in,
                              void* d_out, int out_size) {
    const float* rgb   = (const float*)d_in[0];
    const float* depth = (const float*)d_in[1];
    const float* w1 = (const float*)d_in[2];
    const float* b1 = (const float*)d_in[3];
    const float* w2 = (const float*)d_in[4];
    const float* b2 = (const float*)d_in[5];
    const float* w3 = (const float*)d_in[6];
    const float* b3 = (const float*)d_in[7];
    const float* w4 = (const float*)d_in[8];
    const float* b4 = (const float*)d_in[9];
    const float* w5 = (const float*)d_in[10];
    const float* b5 = (const float*)d_in[11];
    const float* wh = (const float*)d_in[12];
    const float* bh = (const float*)d_in[13];
    const float* wv = (const float*)d_in[14];
    const float* bv = (const float*)d_in[15];

    float* out = (float*)d_out;
    float* fin_o  = out;
    float* blur_o = out + (size_t)B_ * 3 * HW;
    float* kh_o   = out + (size_t)2 * B_ * 3 * HW;
    float* kv_o   = kh_o + (size_t)B_ * KF * HW;
    float* mask_o = kv_o + (size_t)B_ * KF * HW;

    __nv_bfloat16 *bufA, *bufB, *wt2, *wt3, *wt4, *wt5, *wtp;
    cudaGetSymbolAddress((void**)&bufA, g_bufA);
    cudaGetSymbolAddress((void**)&bufB, g_bufB);
    cudaGetSymbolAddress((void**)&wt2, g_wt2);
    cudaGetSymbolAddress((void**)&wt3, g_wt3);
    cudaGetSymbolAddress((void**)&wt4, g_wt4);
    cudaGetSymbolAddress((void**)&wt5, g_wt5);
    cudaGetSymbolAddress((void**)&wtp, g_wtp);

    const int S2 = convmma_smem(64, 64);
    const int S4 = convmma_smem(128, 64);
    const int SP = convmma_smem(64, 32);
    cudaFuncSetAttribute((const void*)convmma_kernel<64, 64, 64, true, false>,
                         cudaFuncAttributeMaxDynamicSharedMemorySize, S2);
    cudaFuncSetAttribute((const void*)convmma_kernel<64, 64, 128, true, false>,
                         cudaFuncAttributeMaxDynamicSharedMemorySize, S2);
    cudaFuncSetAttribute((const void*)convmma_kernel<128, 64, 128, true, false>,
                         cudaFuncAttributeMaxDynamicSharedMemorySize, S4);
    cudaFuncSetAttribute((const void*)convmma_kernel<128, 64, 64, true, false>,
                         cudaFuncAttributeMaxDynamicSharedMemorySize, S4);
    cudaFuncSetAttribute((const void*)convmma_kernel<64, 32, 32, false, true>,
                         cudaFuncAttributeMaxDynamicSharedMemorySize, SP);

    // weight packing
    packw_kernel<64, 64, 64><<<(3 * 96 * 64 * 2 + 255) / 256, 256>>>(w2, wt2);
    packw_kernel<64, 128, 128><<<(3 * 96 * 128 * 2 + 255) / 256, 256>>>(w3, wt3);
    packw_kernel<128, 128, 128><<<(3 * 192 * 128 * 2 + 255) / 256, 256>>>(w4, wt4);
    packw_kernel<128, 64, 64><<<(3 * 192 * 64 * 2 + 255) / 256, 256>>>(w5, wt5);
    packw_p_kernel<<<(3 * 96 * 32 * 2 + 255) / 256, 256>>>(wh, wv, wtp);

    // conv1 fp32 direct -> bf16 NHWC (bufA, 64ch)
    conv1_kernel<<<B_ * HW / 256, 256>>>(rgb, depth, w1, b1, bufA);

    // conv2: 64 -> 64
    convmma_kernel<64, 64, 64, true, false>
        <<<dim3(2, H_, B_), 256, S2>>>(bufA, wt2, b2, bufB);
    // conv3: 64 -> 128 (two 64-wide n-tiles)
    convmma_kernel<64, 64, 128, true, false>
        <<<dim3(2, H_, B_ * 2), 256, S2>>>(bufB, wt3, b3, bufA);
    // conv4: 128 -> 128
    convmma_kernel<128, 64, 128, true, false>
        <<<dim3(2, H_, B_ * 2), 256, S4>>>(bufA, wt4, b4, bufB);
    // conv5: 128 -> 64
    convmma_kernel<128, 64, 64, true, false>
        <<<dim3(2, H_, B_), 256, S4>>>(bufB, wt5, b5, bufA);
    // kpred: 64 -> 32 logits (fp32, no bias/relu) into bufB viewed as float
    convmma_kernel<64, 32, 32, false, true>
        <<<dim3(2, H_, B_), 256, SP>>>(bufA, wtp, nullptr, (float*)bufB);
    // softmax (adds biases) -> kh, kv
    softmax_kernel<<<B_ * HW / 256, 256>>>((const float*)bufB, bh, bv, kh_o, kv_o);

    // blur + composite (bufA region reused as fp32 scratch for hbuf)
    hblur_kernel<<<dim3(H_, B_), 256>>>(rgb, kh_o, (float*)bufA);
    vblur_kernel<<<dim3(H_, B_), 256>>>((float*)bufA, kv_o, rgb, depth, fin_o, blur_o, mask_o);
}

// round 9
// speedup vs baseline: 9.8131x; 1.2202x over previous
#include <cuda_runtime.h>
#include <cuda_bf16.h>
#include <cstdint>
#include <math.h>

#define H_ 256
#define W_ 256
#define B_ 8
#define HW (H_ * W_)
#define KF 11
#define THRESH 0.2f

// ---------------------------------------------------------------------------
// Device scratch (no allocation allowed)
// ---------------------------------------------------------------------------
__device__ __nv_bfloat16 g_bufA[(size_t)B_ * 128 * HW];   // NHWC activations ping
__device__ __nv_bfloat16 g_bufB[(size_t)B_ * 128 * HW];   // NHWC pong / fp32 scratch
// Packed weights: [ky][kp][NP][2] bf16, k = kp*2+h in [0, 3C)
__device__ __nv_bfloat16 g_wt2[3 * 96 * 64 * 2];
__device__ __nv_bfloat16 g_wt3[3 * 96 * 128 * 2];
__device__ __nv_bfloat16 g_wt4[3 * 192 * 128 * 2];
__device__ __nv_bfloat16 g_wt5[3 * 192 * 64 * 2];
__device__ __nv_bfloat16 g_wtp[3 * 96 * 32 * 2];

__device__ __forceinline__ uint32_t smem_u32(const void* p) {
    uint32_t a;
    asm("{ .reg .u64 t; cvta.to.shared.u64 t, %1; cvt.u32.u64 %0, t; }" : "=r"(a) : "l"(p));
    return a;
}

__device__ __forceinline__ void ldmatrix_x4(uint32_t* a, uint32_t addr) {
    asm volatile("ldmatrix.sync.aligned.m8n8.x4.shared.b16 {%0,%1,%2,%3}, [%4];"
                 : "=r"(a[0]), "=r"(a[1]), "=r"(a[2]), "=r"(a[3]) : "r"(addr));
}

__device__ __forceinline__ void mma_bf16(float* d, const uint32_t* a, const uint32_t* b) {
    asm volatile(
        "mma.sync.aligned.m16n8k16.row.col.f32.bf16.bf16.f32 "
        "{%0,%1,%2,%3}, {%4,%5,%6,%7}, {%8,%9}, {%0,%1,%2,%3};"
        : "+f"(d[0]), "+f"(d[1]), "+f"(d[2]), "+f"(d[3])
        : "r"(a[0]), "r"(a[1]), "r"(a[2]), "r"(a[3]), "r"(b[0]), "r"(b[1]));
}

__device__ __forceinline__ void cp16(uint32_t dst, const void* src, bool pred) {
    asm volatile("cp.async.cg.shared.global [%0], [%1], 16, %2;"
                 :: "r"(dst), "l"(src), "r"(pred ? 16 : 0));
}
#define CP_COMMIT() asm volatile("cp.async.commit_group;" ::: "memory")
#define CP_WAIT0()  asm volatile("cp.async.wait_group 0;" ::: "memory")
#define CP_WAIT1()  asm volatile("cp.async.wait_group 1;" ::: "memory")

// ---------------------------------------------------------------------------
// Weight packing (all layers fused into one launch)
// w[COUT][CIN][3][3] fp32 -> wt[ky][kp][NP][2] bf16; k = kp*2+h, kx=k/CIN, ci=k%CIN
// ---------------------------------------------------------------------------
template <int CIN, int COUT, int NP>
__device__ __forceinline__ void packone(const float* __restrict__ w,
                                        __nv_bfloat16* __restrict__ wt, int i) {
    constexpr int KP = 3 * CIN / 2;
    int h = i & 1;
    int n = (i >> 1) % NP;
    int kp = (i >> 1) / NP % KP;
    int ky = i / (2 * NP * KP);
    int k = kp * 2 + h;
    int kx = k / CIN, ci = k % CIN;
    float v = (n < COUT) ? w[((size_t)n * CIN + ci) * 9 + ky * 3 + kx] : 0.f;
    wt[i] = __float2bfloat16(v);
}

__global__ void packall_kernel(const float* __restrict__ w2, const float* __restrict__ w3,
                               const float* __restrict__ w4, const float* __restrict__ w5,
                               const float* __restrict__ wh, const float* __restrict__ wv,
                               __nv_bfloat16* __restrict__ wt2, __nv_bfloat16* __restrict__ wt3,
                               __nv_bfloat16* __restrict__ wt4, __nv_bfloat16* __restrict__ wt5,
                               __nv_bfloat16* __restrict__ wtp) {
    constexpr int N2 = 3 * 96 * 64 * 2;
    constexpr int N3 = 3 * 96 * 128 * 2;
    constexpr int N4 = 3 * 192 * 128 * 2;
    constexpr int N5 = 3 * 192 * 64 * 2;
    constexpr int NPP = 3 * 96 * 32 * 2;
    int i = blockIdx.x * 256 + threadIdx.x;
    if (i < N2) { packone<64, 64, 64>(w2, wt2, i); return; }
    i -= N2;
    if (i < N3) { packone<64, 128, 128>(w3, wt3, i); return; }
    i -= N3;
    if (i < N4) { packone<128, 128, 128>(w4, wt4, i); return; }
    i -= N4;
    if (i < N5) { packone<128, 64, 64>(w5, wt5, i); return; }
    i -= N5;
    if (i < NPP) {
        // kpred: n 0..10 = wh, 11..21 = wv, rest 0 (CIN=64, NP=32)
        constexpr int KP = 96;
        int h = i & 1;
        int n = (i >> 1) % 32;
        int kp = (i >> 1) / 32 % KP;
        int ky = i / (2 * 32 * KP);
        int k = kp * 2 + h;
        int kx = k / 64, ci = k % 64;
        float v = 0.f;
        if (n < KF)          v = wh[((size_t)n * 64 + ci) * 9 + ky * 3 + kx];
        else if (n < 2 * KF) v = wv[((size_t)(n - KF) * 64 + ci) * 9 + ky * 3 + kx];
        wtp[i] = __float2bfloat16(v);
    }
}

// ---------------------------------------------------------------------------
// conv1: 4 -> 64, fp32 direct, NCHW fp32 in -> bf16 NHWC out
// ---------------------------------------------------------------------------
__global__ __launch_bounds__(256)
void conv1_kernel(const float* __restrict__ rgb, const float* __restrict__ depth,
                  const float* __restrict__ w1, const float* __restrict__ b1,
                  __nv_bfloat16* __restrict__ out) {
    __shared__ float sw[64 * 36];
    __shared__ float sb[64];
    int tid = threadIdx.x;
    for (int i = tid; i < 64 * 36; i += 256) sw[i] = w1[i];
    if (tid < 64) sb[tid] = b1[tid];
    __syncthreads();

    int gp = blockIdx.x * 256 + tid;
    int x = gp % W_;
    int y = (gp / W_) % H_;
    int b = gp / HW;

    float acc[64];
#pragma unroll
    for (int o = 0; o < 64; o++) acc[o] = sb[o];

    for (int ci = 0; ci < 4; ci++) {
        const float* plane = (ci < 3) ? rgb + ((size_t)b * 3 + ci) * HW
                                      : depth + (size_t)b * HW;
#pragma unroll
        for (int dy = -1; dy <= 1; dy++) {
#pragma unroll
            for (int dx = -1; dx <= 1; dx++) {
                int yy = y + dy, xx = x + dx;
                float v = (yy >= 0 && yy < H_ && xx >= 0 && xx < W_) ? plane[yy * W_ + xx] : 0.f;
                int widx = ci * 9 + (dy + 1) * 3 + (dx + 1);
#pragma unroll
                for (int o = 0; o < 64; o++) acc[o] = fmaf(sw[o * 36 + widx], v, acc[o]);
            }
        }
    }
    __nv_bfloat16* op = out + (size_t)gp * 64;
#pragma unroll
    for (int o = 0; o < 64; o += 2) {
        __nv_bfloat162 h = __floats2bfloat162_rn(fmaxf(acc[o], 0.f), fmaxf(acc[o + 1], 0.f));
        *(__nv_bfloat162*)(op + o) = h;
    }
}

// ---------------------------------------------------------------------------
// Staging: cp.async one ky row (A im2col strip + B weights) into a stage
// ---------------------------------------------------------------------------
template <int C, int NTILE, int NP>
__device__ __forceinline__ void stage_tiles(const __nv_bfloat16* __restrict__ in,
                                            const __nv_bfloat16* __restrict__ wtP,
                                            uint32_t sA_u, uint32_t sB_u,
                                            int b, int y, int ky, int x0, int n0, int tid) {
    constexpr int SA = C + 8;
    constexpr int BST = NTILE * 2 + 16;
    constexpr int KP3 = 3 * C / 2;
    constexpr int CH8 = C / 8;
    constexpr int NU4 = NTILE / 4;

    const int yy = y + ky - 1;
    const bool rowok = ((unsigned)yy < H_);
    const __nv_bfloat16* inrow = in + (((size_t)b * H_ + (rowok ? yy : 0)) * W_) * C;
    for (int it = tid; it < 130 * CH8; it += 256) {
        int p = it / CH8;
        int c8 = it - p * CH8;
        int xx = x0 + p - 1;
        bool ok = rowok && ((unsigned)xx < W_);
        cp16(sA_u + (p * SA + c8 * 8) * 2, inrow + (size_t)(ok ? xx : 0) * C + c8 * 8, ok);
    }
    const __nv_bfloat16* wsrc = wtP + ((size_t)ky * KP3 * NP + n0) * 2;
    for (int it = tid; it < KP3 * NU4; it += 256) {
        int kp = it / NU4;
        int q = it - kp * NU4;
        cp16(sB_u + (kp * BST + q * 8) * 2, wsrc + (size_t)kp * NP * 2 + q * 8, true);
    }
    CP_COMMIT();
}

// ---------------------------------------------------------------------------
// Compute one ky row's MMA contribution from a stage
// ---------------------------------------------------------------------------
template <int C, int NTILE>
__device__ __forceinline__ void compute_ky(uint32_t sA_u, const char* sB,
                                           int wm, int wn, int lane,
                                           float (*acc)[4] /* [2*NBK][4] */) {
    constexpr int SA = C + 8;
    constexpr int BST = NTILE * 2 + 16;
    constexpr int NSTEP = 3 * C / 16;
    constexpr int KXW = C / 16;
    constexpr int WN = NTILE / 2;
    constexpr int NBK = WN / 8;

    const int lane_row = lane & 15;
    const int colsel = (lane >> 4) * 8;

#pragma unroll
    for (int s = 0; s < NSTEP; s++) {
        const int kx = s / KXW;
        const int c0 = (s - kx * KXW) * 16;
        uint32_t afr[2][4];
#pragma unroll
        for (int mb = 0; mb < 2; mb++) {
            uint32_t addr = sA_u +
                ((wm * 32 + mb * 16 + lane_row + kx) * SA + c0 + colsel) * 2;
            ldmatrix_x4(afr[mb], addr);
        }
        uint32_t bfr[NBK][2];
#pragma unroll
        for (int nb = 0; nb < NBK; nb++) {
            int n = wn * WN + nb * 8 + (lane >> 2);
#pragma unroll
            for (int r = 0; r < 2; r++) {
                int kp = s * 8 + (lane & 3) + r * 4;
                bfr[nb][r] = *(const uint32_t*)(sB + (kp * BST + n * 2) * 2);
            }
        }
#pragma unroll
        for (int mb = 0; mb < 2; mb++)
#pragma unroll
            for (int nb = 0; nb < NBK; nb++)
                mma_bf16(acc[mb * NBK + nb], afr[mb], bfr[nb]);
    }
}

// ---------------------------------------------------------------------------
// Implicit-GEMM 3x3 conv via mma.sync (bf16 HMMA, fp32 acc).
// in: NHWC bf16 [B,H,W,C]; out: NHWC bf16 [B,H,W,NP] (or fp32 if F32OUT).
// CTA: 128 pixels x NTILE. 8 warps: 4(M) x 2(N). DB: double-buffered ky pipeline.
// ---------------------------------------------------------------------------
template <int C, int NTILE, int NP, bool RELU, bool F32OUT, bool DB>
__global__ __launch_bounds__(256)
void convmma_kernel(const __nv_bfloat16* __restrict__ in,
                    const __nv_bfloat16* __restrict__ wtP,
                    const float* __restrict__ bias,
                    void* __restrict__ outv) {
    constexpr int SA = C + 8;
    constexpr int BST = NTILE * 2 + 16;
    constexpr int KP3 = 3 * C / 2;
    constexpr int WN = NTILE / 2;
    constexpr int NBK = WN / 8;
    constexpr int ASZ = 130 * SA * 2;
    constexpr int BSZ = KP3 * BST * 2;
    constexpr int STG = ASZ + BSZ;

    extern __shared__ char smem_raw[];
    char* sA0 = smem_raw;
    char* sB0 = smem_raw + ASZ;
    char* sA1 = smem_raw + (DB ? STG : 0);
    char* sB1 = sA1 + ASZ;
    const uint32_t sA0_u = smem_u32(sA0);
    const uint32_t sB0_u = smem_u32(sB0);
    const uint32_t sA1_u = smem_u32(sA1);
    const uint32_t sB1_u = smem_u32(sB1);

    __shared__ float s_bias[NTILE];

    const int tid = threadIdx.x;
    const int wid = tid >> 5;
    const int lane = tid & 31;
    const int wm = wid & 3;
    const int wn = wid >> 2;
    const int x0 = blockIdx.x * 128;
    const int y = blockIdx.y;
    constexpr int NTILES = NP / NTILE;
    const int b = blockIdx.z / NTILES;
    const int n0 = (blockIdx.z % NTILES) * NTILE;

    if (!F32OUT && tid < NTILE) s_bias[tid] = bias[n0 + tid];

    float acc[2 * NBK][4];
#pragma unroll
    for (int i = 0; i < 2 * NBK; i++)
#pragma unroll
        for (int q = 0; q < 4; q++) acc[i][q] = 0.f;

    if (DB) {
        stage_tiles<C, NTILE, NP>(in, wtP, sA0_u, sB0_u, b, y, 0, x0, n0, tid);
        stage_tiles<C, NTILE, NP>(in, wtP, sA1_u, sB1_u, b, y, 1, x0, n0, tid);
        CP_WAIT1();
        __syncthreads();
        compute_ky<C, NTILE>(sA0_u, sB0, wm, wn, lane, acc);
        __syncthreads();   // protect stage0 before overwrite
        stage_tiles<C, NTILE, NP>(in, wtP, sA0_u, sB0_u, b, y, 2, x0, n0, tid);
        CP_WAIT1();
        __syncthreads();
        compute_ky<C, NTILE>(sA1_u, sB1, wm, wn, lane, acc);
        CP_WAIT0();
        __syncthreads();
        compute_ky<C, NTILE>(sA0_u, sB0, wm, wn, lane, acc);
    } else {
        for (int ky = 0; ky < 3; ky++) {
            if (ky) __syncthreads();
            stage_tiles<C, NTILE, NP>(in, wtP, sA0_u, sB0_u, b, y, ky, x0, n0, tid);
            CP_WAIT0();
            __syncthreads();
            compute_ky<C, NTILE>(sA0_u, sB0, wm, wn, lane, acc);
        }
    }
    __syncthreads();

    // ---- epilogue ----
    const int g = lane >> 2;
    const int cpair = (lane & 3) * 2;
#pragma unroll
    for (int mb = 0; mb < 2; mb++) {
#pragma unroll
        for (int half = 0; half < 2; half++) {
            int m = wm * 32 + mb * 16 + g + half * 8;
            size_t pix = ((size_t)b * H_ + y) * W_ + x0 + m;
#pragma unroll
            for (int nb = 0; nb < NBK; nb++) {
                int col = wn * WN + nb * 8 + cpair;
                float f0 = acc[mb * NBK + nb][half * 2 + 0];
                float f1 = acc[mb * NBK + nb][half * 2 + 1];
                if (F32OUT) {
                    float* op = (float*)outv + pix * NP + n0 + col;
                    *(float2*)op = make_float2(f0, f1);
                } else {
                    f0 += s_bias[col];
                    f1 += s_bias[col + 1];
                    if (RELU) { f0 = fmaxf(f0, 0.f); f1 = fmaxf(f1, 0.f); }
                    __nv_bfloat162 h = __floats2bfloat162_rn(f0, f1);
                    __nv_bfloat16* op = (__nv_bfloat16*)outv + pix * NP + n0 + col;
                    *(uint32_t*)op = *(uint32_t*)&h;
                }
            }
        }
    }
}

// ---------------------------------------------------------------------------
// softmax over logits [B,H,W,32] fp32 -> kh, kv NCHW fp32
// ---------------------------------------------------------------------------
__global__ __launch_bounds__(256)
void softmax_kernel(const float* __restrict__ logits,
                    const float* __restrict__ bh, const float* __restrict__ bv,
                    float* __restrict__ kh_out, float* __restrict__ kv_out) {
    __shared__ float sbh[KF], sbv[KF];
    int tid = threadIdx.x;
    if (tid < KF) { sbh[tid] = bh[tid]; sbv[tid] = bv[tid]; }
    __syncthreads();

    int gp = blockIdx.x * 256 + tid;
    int px = gp % HW;
    int b = gp / HW;
    int y = px / W_, x = px % W_;
    const float* lp = logits + (size_t)gp * 32;

    float l[KF];
#pragma unroll
    for (int i = 0; i < KF; i++) l[i] = lp[i] + sbh[i];
    float mx = l[0];
#pragma unroll
    for (int i = 1; i < KF; i++) mx = fmaxf(mx, l[i]);
    float e[KF], s = 0.f;
#pragma unroll
    for (int i = 0; i < KF; i++) { e[i] = expf(l[i] - mx); s += e[i]; }
    float inv = 1.f / s;
#pragma unroll
    for (int i = 0; i < KF; i++)
        kh_out[(((size_t)b * KF + i) * H_ + y) * W_ + x] = e[i] * inv;

#pragma unroll
    for (int i = 0; i < KF; i++) l[i] = lp[KF + i] + sbv[i];
    mx = l[0];
#pragma unroll
    for (int i = 1; i < KF; i++) mx = fmaxf(mx, l[i]);
    s = 0.f;
#pragma unroll
    for (int i = 0; i < KF; i++) { e[i] = expf(l[i] - mx); s += e[i]; }
    inv = 1.f / s;
#pragma unroll
    for (int i = 0; i < KF; i++)
        kv_out[(((size_t)b * KF + i) * H_ + y) * W_ + x] = e[i] * inv;
}

// ---------------------------------------------------------------------------
// Separable blur + composite (fp32)
// ---------------------------------------------------------------------------
__global__ __launch_bounds__(256)
void hblur_kernel(const float* __restrict__ rgb, const float* __restrict__ kh,
                  float* __restrict__ hout) {
    __shared__ float srow[3][W_ + 10];
    const int x = threadIdx.x;
    const int y = blockIdx.x;
    const int b = blockIdx.y;

#pragma unroll
    for (int c = 0; c < 3; c++)
        srow[c][x + 5] = rgb[(((size_t)b * 3 + c) * H_ + y) * W_ + x];
    if (x < 5) {
#pragma unroll
        for (int c = 0; c < 3; c++) { srow[c][x] = 0.f; srow[c][W_ + 5 + x] = 0.f; }
    }
    __syncthreads();

    float k[KF];
#pragma unroll
    for (int i = 0; i < KF; i++)
        k[i] = kh[(((size_t)b * KF + i) * H_ + y) * W_ + x];

#pragma unroll
    for (int c = 0; c < 3; c++) {
        float s = 0.f;
#pragma unroll
        for (int i = 0; i < KF; i++) s = fmaf(k[i], srow[c][x + i], s);
        hout[(((size_t)b * 3 + c) * H_ + y) * W_ + x] = s;
    }
}

__global__ __launch_bounds__(256)
void vblur_kernel(const float* __restrict__ hbuf, const float* __restrict__ kv,
                  const float* __restrict__ rgb, const float* __restrict__ depth,
                  float* __restrict__ fin, float* __restrict__ blur,
                  float* __restrict__ mask) {
    const int x = threadIdx.x;
    const int y = blockIdx.x;
    const int b = blockIdx.y;

    float k[KF];
#pragma unroll
    for (int i = 0; i < KF; i++)
        k[i] = kv[(((size_t)b * KF + i) * H_ + y) * W_ + x];

    float d = depth[((size_t)b * H_ + y) * W_ + x];
    float m = (d > THRESH) ? 1.f : 0.f;

#pragma unroll
    for (int c = 0; c < 3; c++) {
        float s = 0.f;
#pragma unroll
        for (int i = 0; i < KF; i++) {
            int yy = y - 5 + i;
            if (yy >= 0 && yy < H_)
                s = fmaf(k[i], hbuf[(((size_t)b * 3 + c) * H_ + yy) * W_ + x], s);
        }
        size_t oidx = (((size_t)b * 3 + c) * H_ + y) * W_ + x;
        float r = rgb[oidx];
        blur[oidx] = s;
        fin[oidx] = m * r + (1.f - m) * s;
    }
    mask[((size_t)b * H_ + y) * W_ + x] = m;
}

// ---------------------------------------------------------------------------
static inline int stage_bytes(int C, int NTILE) {
    return 130 * (C + 8) * 2 + (3 * C / 2) * (NTILE * 2 + 16) * 2;
}

extern "C" void kernel_launch(void* const* d_in, const int* in_sizes, int n_in,
                              void* d_out, int out_size) {
    const float* rgb   = (const float*)d_in[0];
    const float* depth = (const float*)d_in[1];
    const float* w1 = (const float*)d_in[2];
    const float* b1 = (const float*)d_in[3];
    const float* w2 = (const float*)d_in[4];
    const float* b2 = (const float*)d_in[5];
    const float* w3 = (const float*)d_in[6];
    const float* b3 = (const float*)d_in[7];
    const float* w4 = (const float*)d_in[8];
    const float* b4 = (const float*)d_in[9];
    const float* w5 = (const float*)d_in[10];
    const float* b5 = (const float*)d_in[11];
    const float* wh = (const float*)d_in[12];
    const float* bh = (const float*)d_in[13];
    const float* wv = (const float*)d_in[14];
    const float* bv = (const float*)d_in[15];

    float* out = (float*)d_out;
    float* fin_o  = out;
    float* blur_o = out + (size_t)B_ * 3 * HW;
    float* kh_o   = out + (size_t)2 * B_ * 3 * HW;
    float* kv_o   = kh_o + (size_t)B_ * KF * HW;
    float* mask_o = kv_o + (size_t)B_ * KF * HW;

    __nv_bfloat16 *bufA, *bufB, *wt2, *wt3, *wt4, *wt5, *wtp;
    cudaGetSymbolAddress((void**)&bufA, g_bufA);
    cudaGetSymbolAddress((void**)&bufB, g_bufB);
    cudaGetSymbolAddress((void**)&wt2, g_wt2);
    cudaGetSymbolAddress((void**)&wt3, g_wt3);
    cudaGetSymbolAddress((void**)&wt4, g_wt4);
    cudaGetSymbolAddress((void**)&wt5, g_wt5);
    cudaGetSymbolAddress((void**)&wtp, g_wtp);

    const int S64  = stage_bytes(64, 64);       // conv2/conv3 stage
    const int S128 = stage_bytes(128, 64);      // conv4/conv5 stage
    const int SPK  = stage_bytes(64, 32);       // kpred stage
    const int S64x2 = 2 * S64;
    const int SPKx2 = 2 * SPK;
    cudaFuncSetAttribute((const void*)convmma_kernel<64, 64, 64, true, false, true>,
                         cudaFuncAttributeMaxDynamicSharedMemorySize, S64x2);
    cudaFuncSetAttribute((const void*)convmma_kernel<64, 64, 128, true, false, true>,
                         cudaFuncAttributeMaxDynamicSharedMemorySize, S64x2);
    cudaFuncSetAttribute((const void*)convmma_kernel<128, 64, 128, true, false, false>,
                         cudaFuncAttributeMaxDynamicSharedMemorySize, S128);
    cudaFuncSetAttribute((const void*)convmma_kernel<128, 64, 64, true, false, false>,
                         cudaFuncAttributeMaxDynamicSharedMemorySize, S128);
    cudaFuncSetAttribute((const void*)convmma_kernel<64, 32, 32, false, true, true>,
                         cudaFuncAttributeMaxDynamicSharedMemorySize, SPKx2);

    // launch 0: fused weight packing
    {
        int total = (3 * 96 * 64 + 3 * 96 * 128 + 3 * 192 * 128 + 3 * 192 * 64 + 3 * 96 * 32) * 2;
        packall_kernel<<<(total + 255) / 256, 256>>>(w2, w3, w4, w5, wh, wv,
                                                     wt2, wt3, wt4, wt5, wtp);
    }
    // launch 1: conv1 fp32 direct -> bf16 NHWC (bufA, 64ch)
    conv1_kernel<<<B_ * HW / 256, 256>>>(rgb, depth, w1, b1, bufA);

    // launch 2: conv2 64->64 (double-buffered)
    convmma_kernel<64, 64, 64, true, false, true>
        <<<dim3(2, H_, B_), 256, S64x2>>>(bufA, wt2, b2, bufB);
    // launch 3: conv3 64->128 (double-buffered)
    convmma_kernel<64, 64, 128, true, false, true>
        <<<dim3(2, H_, B_ * 2), 256, S64x2>>>(bufB, wt3, b3, bufA);
    // launch 4: conv4 128->128 (single-buffered, occ 2)
    convmma_kernel<128, 64, 128, true, false, false>
        <<<dim3(2, H_, B_ * 2), 256, S128>>>(bufA, wt4, b4, bufB);
    // launch 5: conv5 128->64 (single-buffered, occ 2)
    convmma_kernel<128, 64, 64, true, false, false>
        <<<dim3(2, H_, B_), 256, S128>>>(bufB, wt5, b5, bufA);
    // launch 6: kpred 64->32 logits (double-buffered, fp32 out)
    convmma_kernel<64, 32, 32, false, true, true>
        <<<dim3(2, H_, B_), 256, SPKx2>>>(bufA, wtp, nullptr, (float*)bufB);
    // launch 7: softmax
    softmax_kernel<<<B_ * HW / 256, 256>>>((const float*)bufB, bh, bv, kh_o, kv_o);
    // launch 8/9: blur + composite
    hblur_kernel<<<dim3(H_, B_), 256>>>(rgb, kh_o, (float*)bufA);
    vblur_kernel<<<dim3(H_, B_), 256>>>((float*)bufA, kv_o, rgb, depth, fin_o, blur_o, mask_o);
}

// round 10
// speedup vs baseline: 10.3253x; 1.0522x over previous
#include <cuda_runtime.h>
#include <cuda_bf16.h>
#include <cstdint>
#include <math.h>

#define H_ 256
#define W_ 256
#define B_ 8
#define HW (H_ * W_)
#define KF 11
#define THRESH 0.2f

// ---------------------------------------------------------------------------
// Device scratch (no allocation allowed)
// ---------------------------------------------------------------------------
__device__ __nv_bfloat16 g_bufA[(size_t)B_ * 128 * HW];   // NHWC activations ping
__device__ __nv_bfloat16 g_bufB[(size_t)B_ * 128 * HW];   // NHWC pong / fp32 scratch
// Fragment-packed weights: [ky][s][n8][lane] -> uint2 (b0,b1 regs of m16n8k16)
__device__ uint2 g_wt2[3 * 12 * 8 * 32];     // CIN=64,  NP=64
__device__ uint2 g_wt3[3 * 12 * 16 * 32];    // CIN=64,  NP=128
__device__ uint2 g_wt4[3 * 24 * 16 * 32];    // CIN=128, NP=128
__device__ uint2 g_wt5[3 * 24 * 8 * 32];     // CIN=128, NP=64
__device__ uint2 g_wtp[3 * 12 * 4 * 32];     // CIN=64,  NP=32

__device__ __forceinline__ uint32_t smem_u32(const void* p) {
    uint32_t a;
    asm("{ .reg .u64 t; cvta.to.shared.u64 t, %1; cvt.u32.u64 %0, t; }" : "=r"(a) : "l"(p));
    return a;
}

__device__ __forceinline__ void ldmatrix_x4(uint32_t* a, uint32_t addr) {
    asm volatile("ldmatrix.sync.aligned.m8n8.x4.shared.b16 {%0,%1,%2,%3}, [%4];"
                 : "=r"(a[0]), "=r"(a[1]), "=r"(a[2]), "=r"(a[3]) : "r"(addr));
}

__device__ __forceinline__ void mma_bf16(float* d, const uint32_t* a, const uint32_t* b) {
    asm volatile(
        "mma.sync.aligned.m16n8k16.row.col.f32.bf16.bf16.f32 "
        "{%0,%1,%2,%3}, {%4,%5,%6,%7}, {%8,%9}, {%0,%1,%2,%3};"
        : "+f"(d[0]), "+f"(d[1]), "+f"(d[2]), "+f"(d[3])
        : "r"(a[0]), "r"(a[1]), "r"(a[2]), "r"(a[3]), "r"(b[0]), "r"(b[1]));
}

__device__ __forceinline__ void cp16(uint32_t dst, const void* src, bool pred) {
    asm volatile("cp.async.cg.shared.global [%0], [%1], 16, %2;"
                 :: "r"(dst), "l"(src), "r"(pred ? 16 : 0));
}
#define CP_COMMIT() asm volatile("cp.async.commit_group;" ::: "memory")
#define CP_WAIT0()  asm volatile("cp.async.wait_group 0;" ::: "memory")
#define CP_WAIT1()  asm volatile("cp.async.wait_group 1;" ::: "memory")

// ---------------------------------------------------------------------------
// Fragment-order weight packing.
// For step s, n-group n8, lane: b0 = pair(k0, k0+1), b1 = pair(k0+8, k0+9)
// with k0 = s*16 + (lane&3)*2, n = n8*8 + (lane>>2); k -> kx=k/CIN, ci=k%CIN.
// ---------------------------------------------------------------------------
template <int CIN, int COUT, int NP>
__device__ __forceinline__ void packfrag(const float* __restrict__ w, uint2* __restrict__ wt, int i) {
    constexpr int NSTEP = 3 * CIN / 16;
    constexpr int NPG = NP / 8;
    int lane = i & 31;
    int n8 = (i >> 5) % NPG;
    int s = (i >> 5) / NPG % NSTEP;
    int ky = i / (32 * NPG * NSTEP);
    int n = n8 * 8 + (lane >> 2);
    int k0 = s * 16 + (lane & 3) * 2;
    float v[4];
#pragma unroll
    for (int j = 0; j < 4; j++) {
        int k = k0 + (j >> 1) * 8 + (j & 1);
        int kx = k / CIN, ci = k % CIN;
        v[j] = (n < COUT) ? w[((size_t)n * CIN + ci) * 9 + ky * 3 + kx] : 0.f;
    }
    __nv_bfloat162 lo = __floats2bfloat162_rn(v[0], v[1]);
    __nv_bfloat162 hi = __floats2bfloat162_rn(v[2], v[3]);
    uint2 r;
    r.x = *(uint32_t*)&lo;
    r.y = *(uint32_t*)&hi;
    wt[i] = r;
}

__global__ void packall_kernel(const float* __restrict__ w2, const float* __restrict__ w3,
                               const float* __restrict__ w4, const float* __restrict__ w5,
                               const float* __restrict__ wh, const float* __restrict__ wv,
                               uint2* __restrict__ wt2, uint2* __restrict__ wt3,
                               uint2* __restrict__ wt4, uint2* __restrict__ wt5,
                               uint2* __restrict__ wtp) {
    constexpr int N2 = 3 * 12 * 8 * 32;
    constexpr int N3 = 3 * 12 * 16 * 32;
    constexpr int N4 = 3 * 24 * 16 * 32;
    constexpr int N5 = 3 * 24 * 8 * 32;
    constexpr int NPP = 3 * 12 * 4 * 32;
    int i = blockIdx.x * 256 + threadIdx.x;
    if (i < N2) { packfrag<64, 64, 64>(w2, wt2, i); return; }
    i -= N2;
    if (i < N3) { packfrag<64, 128, 128>(w3, wt3, i); return; }
    i -= N3;
    if (i < N4) { packfrag<128, 128, 128>(w4, wt4, i); return; }
    i -= N4;
    if (i < N5) { packfrag<128, 64, 64>(w5, wt5, i); return; }
    i -= N5;
    if (i < NPP) {
        // kpred: n 0..10 = wh, 11..21 = wv, rest 0 (CIN=64, NP=32)
        constexpr int NSTEP = 12, NPG = 4;
        int lane = i & 31;
        int n8 = (i >> 5) % NPG;
        int s = (i >> 5) / NPG % NSTEP;
        int ky = i / (32 * NPG * NSTEP);
        int n = n8 * 8 + (lane >> 2);
        int k0 = s * 16 + (lane & 3) * 2;
        float v[4];
#pragma unroll
        for (int j = 0; j < 4; j++) {
            int k = k0 + (j >> 1) * 8 + (j & 1);
            int kx = k / 64, ci = k % 64;
            float val = 0.f;
            if (n < KF)          val = wh[((size_t)n * 64 + ci) * 9 + ky * 3 + kx];
            else if (n < 2 * KF) val = wv[((size_t)(n - KF) * 64 + ci) * 9 + ky * 3 + kx];
            v[j] = val;
        }
        __nv_bfloat162 lo = __floats2bfloat162_rn(v[0], v[1]);
        __nv_bfloat162 hi = __floats2bfloat162_rn(v[2], v[3]);
        uint2 r;
        r.x = *(uint32_t*)&lo;
        r.y = *(uint32_t*)&hi;
        wtp[i] = r;
    }
}

// ---------------------------------------------------------------------------
// conv1: 4 -> 64, fp32 direct, NCHW fp32 in -> bf16 NHWC out
// ---------------------------------------------------------------------------
__global__ __launch_bounds__(256)
void conv1_kernel(const float* __restrict__ rgb, const float* __restrict__ depth,
                  const float* __restrict__ w1, const float* __restrict__ b1,
                  __nv_bfloat16* __restrict__ out) {
    __shared__ float sw[64 * 36];
    __shared__ float sb[64];
    int tid = threadIdx.x;
    for (int i = tid; i < 64 * 36; i += 256) sw[i] = w1[i];
    if (tid < 64) sb[tid] = b1[tid];
    __syncthreads();

    int gp = blockIdx.x * 256 + tid;
    int x = gp % W_;
    int y = (gp / W_) % H_;
    int b = gp / HW;

    float acc[64];
#pragma unroll
    for (int o = 0; o < 64; o++) acc[o] = sb[o];

    for (int ci = 0; ci < 4; ci++) {
        const float* plane = (ci < 3) ? rgb + ((size_t)b * 3 + ci) * HW
                                      : depth + (size_t)b * HW;
#pragma unroll
        for (int dy = -1; dy <= 1; dy++) {
#pragma unroll
            for (int dx = -1; dx <= 1; dx++) {
                int yy = y + dy, xx = x + dx;
                float v = (yy >= 0 && yy < H_ && xx >= 0 && xx < W_) ? plane[yy * W_ + xx] : 0.f;
                int widx = ci * 9 + (dy + 1) * 3 + (dx + 1);
#pragma unroll
                for (int o = 0; o < 64; o++) acc[o] = fmaf(sw[o * 36 + widx], v, acc[o]);
            }
        }
    }
    __nv_bfloat16* op = out + (size_t)gp * 64;
#pragma unroll
    for (int o = 0; o < 64; o += 2) {
        __nv_bfloat162 h = __floats2bfloat162_rn(fmaxf(acc[o], 0.f), fmaxf(acc[o + 1], 0.f));
        *(__nv_bfloat162*)(op + o) = h;
    }
}

// ---------------------------------------------------------------------------
// Stage one ky row's A im2col strip (130 pixels x C) via cp.async
// ---------------------------------------------------------------------------
template <int C>
__device__ __forceinline__ void stage_A(const __nv_bfloat16* __restrict__ in,
                                        uint32_t sA_u, int b, int y, int ky,
                                        int x0, int tid) {
    constexpr int SA = C + 8;
    constexpr int CH8 = C / 8;
    const int yy = y + ky - 1;
    const bool rowok = ((unsigned)yy < H_);
    const __nv_bfloat16* inrow = in + (((size_t)b * H_ + (rowok ? yy : 0)) * W_) * C;
    for (int it = tid; it < 130 * CH8; it += 256) {
        int p = it / CH8;
        int c8 = it - p * CH8;
        int xx = x0 + p - 1;
        bool ok = rowok && ((unsigned)xx < W_);
        cp16(sA_u + (p * SA + c8 * 8) * 2, inrow + (size_t)(ok ? xx : 0) * C + c8 * 8, ok);
    }
    CP_COMMIT();
}

// ---------------------------------------------------------------------------
// Compute one ky row's MMA contribution: A from smem (ldmatrix), B from gmem
// fragments (__ldg uint2, coalesced, L1/L2-resident).
// ---------------------------------------------------------------------------
template <int C, int NTILE, int NP>
__device__ __forceinline__ void compute_ky(uint32_t sA_u, const uint2* __restrict__ wtF,
                                           int ky, int n8_0, int wm, int wn, int lane,
                                           float (*acc)[4] /* [2*NBK][4] */) {
    constexpr int SA = C + 8;
    constexpr int NSTEP = 3 * C / 16;
    constexpr int KXW = C / 16;
    constexpr int WN = NTILE / 2;
    constexpr int NBK = WN / 8;
    constexpr int NPG = NP / 8;

    const int lane_row = lane & 15;
    const int colsel = (lane >> 4) * 8;
    const uint2* wbase = wtF + ((size_t)ky * NSTEP * NPG + n8_0 + wn * NBK) * 32 + lane;

#pragma unroll
    for (int s = 0; s < NSTEP; s++) {
        const int kx = s / KXW;
        const int c0 = (s - kx * KXW) * 16;
        uint32_t afr[2][4];
#pragma unroll
        for (int mb = 0; mb < 2; mb++) {
            uint32_t addr = sA_u +
                ((wm * 32 + mb * 16 + lane_row + kx) * SA + c0 + colsel) * 2;
            ldmatrix_x4(afr[mb], addr);
        }
        uint32_t bfr[NBK][2];
#pragma unroll
        for (int nb = 0; nb < NBK; nb++) {
            uint2 bv = __ldg(wbase + ((size_t)s * NPG + nb) * 32);
            bfr[nb][0] = bv.x;
            bfr[nb][1] = bv.y;
        }
#pragma unroll
        for (int mb = 0; mb < 2; mb++)
#pragma unroll
            for (int nb = 0; nb < NBK; nb++)
                mma_bf16(acc[mb * NBK + nb], afr[mb], bfr[nb]);
    }
}

// ---------------------------------------------------------------------------
// Implicit-GEMM 3x3 conv via mma.sync. Double-buffered ky pipeline; smem = A only.
// ---------------------------------------------------------------------------
template <int C, int NTILE, int NP, bool RELU, bool F32OUT>
__global__ __launch_bounds__(256)
void convmma_kernel(const __nv_bfloat16* __restrict__ in,
                    const uint2* __restrict__ wtF,
                    const float* __restrict__ bias,
                    void* __restrict__ outv) {
    constexpr int SA = C + 8;
    constexpr int WN = NTILE / 2;
    constexpr int NBK = WN / 8;
    constexpr int ASZ = 130 * SA * 2;

    extern __shared__ char smem_raw[];
    const uint32_t sA0_u = smem_u32(smem_raw);
    const uint32_t sA1_u = sA0_u + ASZ;

    __shared__ float s_bias[NTILE];

    const int tid = threadIdx.x;
    const int wid = tid >> 5;
    const int lane = tid & 31;
    const int wm = wid & 3;
    const int wn = wid >> 2;
    const int x0 = blockIdx.x * 128;
    const int y = blockIdx.y;
    constexpr int NTILES = NP / NTILE;
    const int b = blockIdx.z / NTILES;
    const int n0 = (blockIdx.z % NTILES) * NTILE;
    const int n8_0 = n0 / 8;

    if (!F32OUT && tid < NTILE) s_bias[tid] = bias[n0 + tid];

    float acc[2 * NBK][4];
#pragma unroll
    for (int i = 0; i < 2 * NBK; i++)
#pragma unroll
        for (int q = 0; q < 4; q++) acc[i][q] = 0.f;

    stage_A<C>(in, sA0_u, b, y, 0, x0, tid);
    stage_A<C>(in, sA1_u, b, y, 1, x0, tid);
    CP_WAIT1();
    __syncthreads();
    compute_ky<C, NTILE, NP>(sA0_u, wtF, 0, n8_0, wm, wn, lane, acc);
    __syncthreads();   // protect stage0 before overwrite
    stage_A<C>(in, sA0_u, b, y, 2, x0, tid);
    CP_WAIT1();
    __syncthreads();
    compute_ky<C, NTILE, NP>(sA1_u, wtF, 1, n8_0, wm, wn, lane, acc);
    CP_WAIT0();
    __syncthreads();
    compute_ky<C, NTILE, NP>(sA0_u, wtF, 2, n8_0, wm, wn, lane, acc);
    __syncthreads();

    // ---- epilogue ----
    const int g = lane >> 2;
    const int cpair = (lane & 3) * 2;
#pragma unroll
    for (int mb = 0; mb < 2; mb++) {
#pragma unroll
        for (int half = 0; half < 2; half++) {
            int m = wm * 32 + mb * 16 + g + half * 8;
            size_t pix = ((size_t)b * H_ + y) * W_ + x0 + m;
#pragma unroll
            for (int nb = 0; nb < NBK; nb++) {
                int col = wn * WN + nb * 8 + cpair;
                float f0 = acc[mb * NBK + nb][half * 2 + 0];
                float f1 = acc[mb * NBK + nb][half * 2 + 1];
                if (F32OUT) {
                    float* op = (float*)outv + pix * NP + n0 + col;
                    *(float2*)op = make_float2(f0, f1);
                } else {
                    f0 += s_bias[col];
                    f1 += s_bias[col + 1];
                    if (RELU) { f0 = fmaxf(f0, 0.f); f1 = fmaxf(f1, 0.f); }
                    __nv_bfloat162 h = __floats2bfloat162_rn(f0, f1);
                    __nv_bfloat16* op = (__nv_bfloat16*)outv + pix * NP + n0 + col;
                    *(uint32_t*)op = *(uint32_t*)&h;
                }
            }
        }
    }
}

// ---------------------------------------------------------------------------
// softmax over logits [B,H,W,32] fp32 -> kh, kv NCHW fp32
// ---------------------------------------------------------------------------
__global__ __launch_bounds__(256)
void softmax_kernel(const float* __restrict__ logits,
                    const float* __restrict__ bh, const float* __restrict__ bv,
                    float* __restrict__ kh_out, float* __restrict__ kv_out) {
    __shared__ float sbh[KF], sbv[KF];
    int tid = threadIdx.x;
    if (tid < KF) { sbh[tid] = bh[tid]; sbv[tid] = bv[tid]; }
    __syncthreads();

    int gp = blockIdx.x * 256 + tid;
    int px = gp % HW;
    int b = gp / HW;
    int y = px / W_, x = px % W_;
    const float* lp = logits + (size_t)gp * 32;

    float l[KF];
#pragma unroll
    for (int i = 0; i < KF; i++) l[i] = lp[i] + sbh[i];
    float mx = l[0];
#pragma unroll
    for (int i = 1; i < KF; i++) mx = fmaxf(mx, l[i]);
    float e[KF], s = 0.f;
#pragma unroll
    for (int i = 0; i < KF; i++) { e[i] = expf(l[i] - mx); s += e[i]; }
    float inv = 1.f / s;
#pragma unroll
    for (int i = 0; i < KF; i++)
        kh_out[(((size_t)b * KF + i) * H_ + y) * W_ + x] = e[i] * inv;

#pragma unroll
    for (int i = 0; i < KF; i++) l[i] = lp[KF + i] + sbv[i];
    mx = l[0];
#pragma unroll
    for (int i = 1; i < KF; i++) mx = fmaxf(mx, l[i]);
    s = 0.f;
#pragma unroll
    for (int i = 0; i < KF; i++) { e[i] = expf(l[i] - mx); s += e[i]; }
    inv = 1.f / s;
#pragma unroll
    for (int i = 0; i < KF; i++)
        kv_out[(((size_t)b * KF + i) * H_ + y) * W_ + x] = e[i] * inv;
}

// ---------------------------------------------------------------------------
// Separable blur + composite (fp32)
// ---------------------------------------------------------------------------
__global__ __launch_bounds__(256)
void hblur_kernel(const float* __restrict__ rgb, const float* __restrict__ kh,
                  float* __restrict__ hout) {
    __shared__ float srow[3][W_ + 10];
    const int x = threadIdx.x;
    const int y = blockIdx.x;
    const int b = blockIdx.y;

#pragma unroll
    for (int c = 0; c < 3; c++)
        srow[c][x + 5] = rgb[(((size_t)b * 3 + c) * H_ + y) * W_ + x];
    if (x < 5) {
#pragma unroll
        for (int c = 0; c < 3; c++) { srow[c][x] = 0.f; srow[c][W_ + 5 + x] = 0.f; }
    }
    __syncthreads();

    float k[KF];
#pragma unroll
    for (int i = 0; i < KF; i++)
        k[i] = kh[(((size_t)b * KF + i) * H_ + y) * W_ + x];

#pragma unroll
    for (int c = 0; c < 3; c++) {
        float s = 0.f;
#pragma unroll
        for (int i = 0; i < KF; i++) s = fmaf(k[i], srow[c][x + i], s);
        hout[(((size_t)b * 3 + c) * H_ + y) * W_ + x] = s;
    }
}

__global__ __launch_bounds__(256)
void vblur_kernel(const float* __restrict__ hbuf, const float* __restrict__ kv,
                  const float* __restrict__ rgb, const float* __restrict__ depth,
                  float* __restrict__ fin, float* __restrict__ blur,
                  float* __restrict__ mask) {
    const int x = threadIdx.x;
    const int y = blockIdx.x;
    const int b = blockIdx.y;

    float k[KF];
#pragma unroll
    for (int i = 0; i < KF; i++)
        k[i] = kv[(((size_t)b * KF + i) * H_ + y) * W_ + x];

    float d = depth[((size_t)b * H_ + y) * W_ + x];
    float m = (d > THRESH) ? 1.f : 0.f;

#pragma unroll
    for (int c = 0; c < 3; c++) {
        float s = 0.f;
#pragma unroll
        for (int i = 0; i < KF; i++) {
            int yy = y - 5 + i;
            if (yy >= 0 && yy < H_)
                s = fmaf(k[i], hbuf[(((size_t)b * 3 + c) * H_ + yy) * W_ + x], s);
        }
        size_t oidx = (((size_t)b * 3 + c) * H_ + y) * W_ + x;
        float r = rgb[oidx];
        blur[oidx] = s;
        fin[oidx] = m * r + (1.f - m) * s;
    }
    mask[((size_t)b * H_ + y) * W_ + x] = m;
}

// ---------------------------------------------------------------------------
extern "C" void kernel_launch(void* const* d_in, const int* in_sizes, int n_in,
                              void* d_out, int out_size) {
    const float* rgb   = (const float*)d_in[0];
    const float* depth = (const float*)d_in[1];
    const float* w1 = (const float*)d_in[2];
    const float* b1 = (const float*)d_in[3];
    const float* w2 = (const float*)d_in[4];
    const float* b2 = (const float*)d_in[5];
    const float* w3 = (const float*)d_in[6];
    const float* b3 = (const float*)d_in[7];
    const float* w4 = (const float*)d_in[8];
    const float* b4 = (const float*)d_in[9];
    const float* w5 = (const float*)d_in[10];
    const float* b5 = (const float*)d_in[11];
    const float* wh = (const float*)d_in[12];
    const float* bh = (const float*)d_in[13];
    const float* wv = (const float*)d_in[14];
    const float* bv = (const float*)d_in[15];

    float* out = (float*)d_out;
    float* fin_o  = out;
    float* blur_o = out + (size_t)B_ * 3 * HW;
    float* kh_o   = out + (size_t)2 * B_ * 3 * HW;
    float* kv_o   = kh_o + (size_t)B_ * KF * HW;
    float* mask_o = kv_o + (size_t)B_ * KF * HW;

    __nv_bfloat16 *bufA, *bufB;
    uint2 *wt2, *wt3, *wt4, *wt5, *wtp;
    cudaGetSymbolAddress((void**)&bufA, g_bufA);
    cudaGetSymbolAddress((void**)&bufB, g_bufB);
    cudaGetSymbolAddress((void**)&wt2, g_wt2);
    cudaGetSymbolAddress((void**)&wt3, g_wt3);
    cudaGetSymbolAddress((void**)&wt4, g_wt4);
    cudaGetSymbolAddress((void**)&wt5, g_wt5);
    cudaGetSymbolAddress((void**)&wtp, g_wtp);

    const int S64  = 2 * 130 * (64 + 8) * 2;    // 2-stage A, C=64
    const int S128 = 2 * 130 * (128 + 8) * 2;   // 2-stage A, C=128
    cudaFuncSetAttribute((const void*)convmma_kernel<64, 64, 64, true, false>,
                         cudaFuncAttributeMaxDynamicSharedMemorySize, S64);
    cudaFuncSetAttribute((const void*)convmma_kernel<64, 64, 128, true, false>,
                         cudaFuncAttributeMaxDynamicSharedMemorySize, S64);
    cudaFuncSetAttribute((const void*)convmma_kernel<128, 64, 128, true, false>,
                         cudaFuncAttributeMaxDynamicSharedMemorySize, S128);
    cudaFuncSetAttribute((const void*)convmma_kernel<128, 64, 64, true, false>,
                         cudaFuncAttributeMaxDynamicSharedMemorySize, S128);
    cudaFuncSetAttribute((const void*)convmma_kernel<64, 32, 32, false, true>,
                         cudaFuncAttributeMaxDynamicSharedMemorySize, S64);

    // launch 0: fused fragment-order weight packing
    {
        int total = (3 * 12 * 8 + 3 * 12 * 16 + 3 * 24 * 16 + 3 * 24 * 8 + 3 * 12 * 4) * 32;
        packall_kernel<<<(total + 255) / 256, 256>>>(w2, w3, w4, w5, wh, wv,
                                                     wt2, wt3, wt4, wt5, wtp);
    }
    // launch 1: conv1 fp32 direct -> bf16 NHWC (bufA, 64ch)
    conv1_kernel<<<B_ * HW / 256, 256>>>(rgb, depth, w1, b1, bufA);

    // launch 2: conv2 64->64
    convmma_kernel<64, 64, 64, true, false>
        <<<dim3(2, H_, B_), 256, S64>>>(bufA, wt2, b2, bufB);
    // launch 3: conv3 64->128
    convmma_kernel<64, 64, 128, true, false>
        <<<dim3(2, H_, B_ * 2), 256, S64>>>(bufB, wt3, b3, bufA);
    // launch 4: conv4 128->128
    convmma_kernel<128, 64, 128, true, false>
        <<<dim3(2, H_, B_ * 2), 256, S128>>>(bufA, wt4, b4, bufB);
    // launch 5: conv5 128->64
    convmma_kernel<128, 64, 64, true, false>
        <<<dim3(2, H_, B_), 256, S128>>>(bufB, wt5, b5, bufA);
    // launch 6: kpred 64->32 logits (fp32 out)
    convmma_kernel<64, 32, 32, false, true>
        <<<dim3(2, H_, B_), 256, S64>>>(bufA, wtp, nullptr, (float*)bufB);
    // launch 7: softmax
    softmax_kernel<<<B_ * HW / 256, 256>>>((const float*)bufB, bh, bv, kh_o, kv_o);
    // launch 8/9: blur + composite
    hblur_kernel<<<dim3(H_, B_), 256>>>(rgb, kh_o, (float*)bufA);
    vblur_kernel<<<dim3(H_, B_), 256>>>((float*)bufA, kv_o, rgb, depth, fin_o, blur_o, mask_o);
}